// round 1
// baseline (speedup 1.0000x reference)
#include <cuda_runtime.h>
#include <math.h>

// ---------------- problem constants ----------------
constexpr int T    = 2048;         // tokens
constexpr int HID  = 4096;         // hidden
constexpr int NH   = 32;           // heads
constexpr int DQ   = 256;          // q/k head dim
constexpr int DN   = 192;          // nope dim
constexpr int DR   = 64;           // rope dim
constexpr int DV   = 256;          // v head dim
constexpr int DKV  = 512;          // kv latent
constexpr int QLORA= 2048;         // q lora rank
constexpr int HDQ  = NH * DQ;      // 8192
constexpr int KVW  = NH * (DN + DV); // 14336
constexpr int LATW = DKV + DR;     // 576

// ---------------- scratch (device globals; no cudaMalloc allowed) ----------------
__device__ float g_qlora[(size_t)T * QLORA];     // 16 MB
__device__ float g_latent[(size_t)T * LATW];     // 4.7 MB
__device__ float g_q[(size_t)T * HDQ];           // 64 MB
__device__ float g_kv[(size_t)T * KVW];          // 117 MB
__device__ float g_K[(size_t)T * HDQ];           // 64 MB
__device__ float g_S[(size_t)NH * T * T];        // 512 MB
__device__ float g_O[(size_t)T * HDQ];           // 64 MB

// ---------------- generic batched SGEMM (row-major), NN: C = A[M,K] @ B[K,N] ----------------
constexpr int BM = 128, BN = 128, BK = 8, TM = 8, TN = 8; // 256 threads

__global__ __launch_bounds__(256) void sgemm_nn(
    const float* __restrict__ A, const float* __restrict__ B, float* __restrict__ C,
    int M, int N, int K, int lda, int ldb, int ldc,
    long sA, long sB, long sC, int truncK)
{
    A += (long)blockIdx.z * sA;
    B += (long)blockIdx.z * sB;
    C += (long)blockIdx.z * sC;
    const int bx = blockIdx.x, by = blockIdx.y;
    if (truncK) { int ke = (by + 1) * BM; if (ke < K) K = ke; }

    __shared__ float As[BK][BM];
    __shared__ float Bs[BK][BN + 4];

    const int tid  = threadIdx.x;
    const int trow = tid >> 4;         // 0..15
    const int tcol = tid & 15;         // 0..15

    float acc[TM][TN] = {};

    const int aRow = tid >> 1;          // 0..127
    const int aCol = (tid & 1) * 4;     // 0 or 4
    const int bRow = tid >> 5;          // 0..7
    const int bCol = (tid & 31) * 4;    // 0..124
    const int rowA  = by * BM + aRow;
    const int bColG = bx * BN + bCol;

    const float* Aptr = A + (long)rowA * lda + aCol;
    const float* Bptr = B + (long)bRow * ldb + bColG;

    for (int k0 = 0; k0 < K; k0 += BK) {
        #pragma unroll
        for (int i = 0; i < 4; i++) {
            float v = 0.f;
            if (rowA < M) v = Aptr[k0 + i];
            As[aCol + i][aRow] = v;
        }
        {
            float4 bv;
            if (bColG + 3 < N) {
                bv = *(const float4*)(Bptr + (long)k0 * ldb);
            } else {
                float t0 = (bColG + 0 < N) ? Bptr[(long)k0 * ldb + 0] : 0.f;
                float t1 = (bColG + 1 < N) ? Bptr[(long)k0 * ldb + 1] : 0.f;
                float t2 = (bColG + 2 < N) ? Bptr[(long)k0 * ldb + 2] : 0.f;
                float t3 = (bColG + 3 < N) ? Bptr[(long)k0 * ldb + 3] : 0.f;
                bv = make_float4(t0, t1, t2, t3);
            }
            *(float4*)&Bs[bRow][bCol] = bv;
        }
        __syncthreads();

        #pragma unroll
        for (int kk = 0; kk < BK; kk++) {
            float ra[TM], rb[TN];
            #pragma unroll
            for (int i = 0; i < TM; i++) ra[i] = As[kk][trow * TM + i];
            #pragma unroll
            for (int j = 0; j < TN; j++) rb[j] = Bs[kk][tcol * TN + j];
            #pragma unroll
            for (int i = 0; i < TM; i++)
                #pragma unroll
                for (int j = 0; j < TN; j++) acc[i][j] += ra[i] * rb[j];
        }
        __syncthreads();
    }

    #pragma unroll
    for (int i = 0; i < TM; i++) {
        int r = by * BM + trow * TM + i;
        if (r >= M) continue;
        #pragma unroll
        for (int j = 0; j < TN; j += 4) {
            int c = bx * BN + tcol * TN + j;
            if (c + 3 < N) {
                *(float4*)&C[(long)r * ldc + c] =
                    make_float4(acc[i][j], acc[i][j+1], acc[i][j+2], acc[i][j+3]);
            } else {
                for (int qq = 0; qq < 4; qq++)
                    if (c + qq < N) C[(long)r * ldc + c + qq] = acc[i][j + qq];
            }
        }
    }
}

// NT: C = A[M,K] @ B[N,K]^T  (B row-major [N,K]); optional causal block skip (needs BM==BN)
__global__ __launch_bounds__(256) void sgemm_nt(
    const float* __restrict__ A, const float* __restrict__ B, float* __restrict__ C,
    int M, int N, int K, int lda, int ldb, int ldc,
    long sA, long sB, long sC, int causal)
{
    const int bx = blockIdx.x, by = blockIdx.y;
    if (causal && bx > by) return;   // block entirely above the diagonal

    A += (long)blockIdx.z * sA;
    B += (long)blockIdx.z * sB;
    C += (long)blockIdx.z * sC;

    __shared__ float As[BK][BM];
    __shared__ float Bs[BK][BN + 4];

    const int tid  = threadIdx.x;
    const int trow = tid >> 4;
    const int tcol = tid & 15;

    float acc[TM][TN] = {};

    const int aRow = tid >> 1;
    const int aCol = (tid & 1) * 4;
    const int rowA = by * BM + aRow;
    const int rowB = bx * BN + aRow;

    const float* Aptr = A + (long)rowA * lda + aCol;
    const float* Bptr = B + (long)rowB * ldb + aCol;

    for (int k0 = 0; k0 < K; k0 += BK) {
        #pragma unroll
        for (int i = 0; i < 4; i++) {
            As[aCol + i][aRow] = (rowA < M) ? Aptr[k0 + i] : 0.f;
            Bs[aCol + i][aRow] = (rowB < N) ? Bptr[k0 + i] : 0.f;
        }
        __syncthreads();

        #pragma unroll
        for (int kk = 0; kk < BK; kk++) {
            float ra[TM], rb[TN];
            #pragma unroll
            for (int i = 0; i < TM; i++) ra[i] = As[kk][trow * TM + i];
            #pragma unroll
            for (int j = 0; j < TN; j++) rb[j] = Bs[kk][tcol * TN + j];
            #pragma unroll
            for (int i = 0; i < TM; i++)
                #pragma unroll
                for (int j = 0; j < TN; j++) acc[i][j] += ra[i] * rb[j];
        }
        __syncthreads();
    }

    #pragma unroll
    for (int i = 0; i < TM; i++) {
        int r = by * BM + trow * TM + i;
        if (r >= M) continue;
        #pragma unroll
        for (int j = 0; j < TN; j += 4) {
            int c = bx * BN + tcol * TN + j;
            if (c + 3 < N) {
                *(float4*)&C[(long)r * ldc + c] =
                    make_float4(acc[i][j], acc[i][j+1], acc[i][j+2], acc[i][j+3]);
            } else {
                for (int qq = 0; qq < 4; qq++)
                    if (c + qq < N) C[(long)r * ldc + c + qq] = acc[i][j + qq];
            }
        }
    }
}

// ---------------- RMSNorm (in place, first N cols of each row, row stride ld) ----------------
__global__ void rmsnorm_k(float* __restrict__ x, const float* __restrict__ w, int N, int ld)
{
    float* p = x + (long)blockIdx.x * ld;
    __shared__ float red[8];
    __shared__ float bc;
    const int lane = threadIdx.x & 31, wid = threadIdx.x >> 5;

    float s = 0.f;
    for (int j = threadIdx.x; j < N; j += blockDim.x) { float v = p[j]; s += v * v; }
    #pragma unroll
    for (int o = 16; o; o >>= 1) s += __shfl_xor_sync(0xffffffffu, s, o);
    if (lane == 0) red[wid] = s;
    __syncthreads();
    if (threadIdx.x == 0) {
        float v = 0.f;
        for (int wI = 0; wI < 8; wI++) v += red[wI];
        bc = rsqrtf(v / N + 1e-6f);
    }
    __syncthreads();
    float r = bc;
    for (int j = threadIdx.x; j < N; j += blockDim.x) p[j] = p[j] * r * w[j];
}

// ---------------- neox RoPE ----------------
__global__ void rope_q_k(float* __restrict__ q, const int* __restrict__ pos)
{
    const int t = blockIdx.x, h = blockIdx.y, i = threadIdx.x;   // i < 32
    double inv = pow(10000.0, -(double)i / 32.0);
    double sd, cd;
    sincos((double)pos[t] * inv, &sd, &cd);
    float c = (float)cd, s = (float)sd;
    float* p = q + (long)t * HDQ + h * DQ + DN;
    float x1 = p[i], x2 = p[i + 32];
    p[i]      = x1 * c - x2 * s;
    p[i + 32] = x2 * c + x1 * s;
}

__global__ void rope_kpe_k(float* __restrict__ lat, const int* __restrict__ pos)
{
    const int t = blockIdx.x, i = threadIdx.x;   // i < 32
    double inv = pow(10000.0, -(double)i / 32.0);
    double sd, cd;
    sincos((double)pos[t] * inv, &sd, &cd);
    float c = (float)cd, s = (float)sd;
    float* p = lat + (long)t * LATW + DKV;
    float x1 = p[i], x2 = p[i + 32];
    p[i]      = x1 * c - x2 * s;
    p[i + 32] = x2 * c + x1 * s;
}

// ---------------- assemble K = [k_nope | roped k_pe] as [T, H*256] ----------------
__global__ void build_K_k(const float* __restrict__ kv, const float* __restrict__ lat,
                          float* __restrict__ Kc)
{
    const int t = blockIdx.x;
    for (int x = threadIdx.x; x < HDQ; x += blockDim.x) {
        int h = x >> 8, d = x & 255;
        float v = (d < DN) ? kv[(long)t * KVW + h * (DN + DV) + d]
                           : lat[(long)t * LATW + DKV + (d - DN)];
        Kc[(long)t * HDQ + x] = v;
    }
}

// ---------------- causal softmax (in place, row = keys 0..t, zeros beyond) ----------------
__global__ void softmax_causal_k(float* __restrict__ S)
{
    const float scale = 0.0625f;   // DQ^-0.5 = 1/16
    const int t = blockIdx.x, h = blockIdx.y;
    float* row = S + ((long)h * T + t) * (long)T;
    const int n = t + 1;
    __shared__ float red[8];
    __shared__ float bc;
    const int lane = threadIdx.x & 31, wid = threadIdx.x >> 5;

    float m = -3.4e38f;
    for (int j = threadIdx.x; j < n; j += blockDim.x) m = fmaxf(m, row[j]);
    #pragma unroll
    for (int o = 16; o; o >>= 1) m = fmaxf(m, __shfl_xor_sync(0xffffffffu, m, o));
    if (lane == 0) red[wid] = m;
    __syncthreads();
    if (threadIdx.x == 0) {
        float v = red[0];
        for (int wI = 1; wI < 8; wI++) v = fmaxf(v, red[wI]);
        bc = v;
    }
    __syncthreads();
    m = bc;
    __syncthreads();

    float s = 0.f;
    for (int j = threadIdx.x; j < n; j += blockDim.x) {
        float e = expf((row[j] - m) * scale);
        row[j] = e;
        s += e;
    }
    #pragma unroll
    for (int o = 16; o; o >>= 1) s += __shfl_xor_sync(0xffffffffu, s, o);
    if (lane == 0) red[wid] = s;
    __syncthreads();
    if (threadIdx.x == 0) {
        float v = 0.f;
        for (int wI = 0; wI < 8; wI++) v += red[wI];
        bc = 1.f / v;
    }
    __syncthreads();
    float inv = bc;
    for (int j = threadIdx.x; j < n; j += blockDim.x) row[j] *= inv;
    for (int j = n + threadIdx.x; j < T; j += blockDim.x) row[j] = 0.f;
}

// ---------------- launch ----------------
extern "C" void kernel_launch(void* const* d_in, const int* in_sizes, int n_in,
                              void* d_out, int out_size)
{
    (void)in_sizes; (void)n_in; (void)out_size;
    const float* hidden = (const float*)d_in[0];
    const int*   pos    = (const int*)  d_in[1];
    const float* wq_a   = (const float*)d_in[2];
    const float* q_ln   = (const float*)d_in[3];
    const float* wq_b   = (const float*)d_in[4];
    const float* wkv_a  = (const float*)d_in[5];
    const float* kv_ln  = (const float*)d_in[6];
    const float* wkv_b  = (const float*)d_in[7];
    const float* wo     = (const float*)d_in[8];
    float* out = (float*)d_out;

    float *qlora, *latent, *q, *kv, *Kc, *S, *O;
    cudaGetSymbolAddress((void**)&qlora,  g_qlora);
    cudaGetSymbolAddress((void**)&latent, g_latent);
    cudaGetSymbolAddress((void**)&q,      g_q);
    cudaGetSymbolAddress((void**)&kv,     g_kv);
    cudaGetSymbolAddress((void**)&Kc,     g_K);
    cudaGetSymbolAddress((void**)&S,      g_S);
    cudaGetSymbolAddress((void**)&O,      g_O);

    dim3 blk(256);

    // q lora down + kv latent down
    sgemm_nn<<<dim3(QLORA / BN, T / BM, 1), blk>>>(hidden, wq_a, qlora,
        T, QLORA, HID, HID, QLORA, QLORA, 0, 0, 0, 0);
    sgemm_nn<<<dim3((LATW + BN - 1) / BN, T / BM, 1), blk>>>(hidden, wkv_a, latent,
        T, LATW, HID, HID, LATW, LATW, 0, 0, 0, 0);

    // rmsnorms
    rmsnorm_k<<<T, 256>>>(qlora, q_ln, QLORA, QLORA);
    rmsnorm_k<<<T, 256>>>(latent, kv_ln, DKV, LATW);

    // up projections
    sgemm_nn<<<dim3(HDQ / BN, T / BM, 1), blk>>>(qlora, wq_b, q,
        T, HDQ, QLORA, QLORA, HDQ, HDQ, 0, 0, 0, 0);
    sgemm_nn<<<dim3(KVW / BN, T / BM, 1), blk>>>(latent, wkv_b, kv,
        T, KVW, DKV, LATW, KVW, KVW, 0, 0, 0, 0);

    // rope (q_pe per head, shared k_pe)
    rope_q_k<<<dim3(T, NH), 32>>>(q, pos);
    rope_kpe_k<<<T, 32>>>(latent, pos);

    // assemble K [T, H*256]
    build_K_k<<<T, 256>>>(kv, latent, Kc);

    // scores: S_h = Q_h @ K_h^T   (batched over heads, causal block skip)
    sgemm_nt<<<dim3(T / BN, T / BM, NH), blk>>>(q, Kc, S,
        T, T, DQ, HDQ, HDQ, T, (long)DQ, (long)DQ, (long)T * T, 1);

    // causal softmax
    softmax_causal_k<<<dim3(T, NH), 256>>>(S);

    // O_h = P_h @ V_h  (V viewed in-place inside kv; truncate K-loop causally)
    sgemm_nn<<<dim3(DV / BN, T / BM, NH), blk>>>(S, kv + DN, O,
        T, DV, T, T, KVW, HDQ, (long)T * T, (long)(DN + DV), (long)DV, 1);

    // final projection
    sgemm_nn<<<dim3(HID / BN, T / BM, 1), blk>>>(O, wo, out,
        T, HID, HDQ, HDQ, HID, HID, 0, 0, 0, 0);
}

// round 2
// speedup vs baseline: 2.1709x; 2.1709x over previous
#include <cuda_runtime.h>
#include <cuda_bf16.h>
#include <math.h>
#include <stdint.h>

// ---------------- problem constants ----------------
constexpr int T    = 2048;
constexpr int HID  = 4096;
constexpr int NH   = 32;
constexpr int DQ   = 256;
constexpr int DN   = 192;
constexpr int DR   = 64;
constexpr int DV   = 256;
constexpr int DKV  = 512;
constexpr int QLORA= 2048;
constexpr int HDQ  = NH * DQ;        // 8192
constexpr int KVW  = NH * (DN + DV); // 14336
constexpr int LATW = DKV + DR;       // 576

// ---------------- scratch ----------------
__device__ float g_qlora[(size_t)T * QLORA];
__device__ float g_latent[(size_t)T * LATW];
__device__ float g_q[(size_t)T * HDQ];
__device__ float g_kv[(size_t)T * KVW];
__device__ float g_K[(size_t)T * HDQ];
__device__ float g_S[(size_t)NH * T * T];
__device__ float g_O[(size_t)T * HDQ];

// ---------------- helpers ----------------
__device__ __forceinline__ void split2(float x, float y, uint32_t& hi, uint32_t& lo) {
    __nv_bfloat16 hx = __float2bfloat16_rn(x);
    __nv_bfloat16 hy = __float2bfloat16_rn(y);
    float rx = x - __bfloat162float(hx);
    float ry = y - __bfloat162float(hy);
    __nv_bfloat16 lx = __float2bfloat16_rn(rx);
    __nv_bfloat16 ly = __float2bfloat16_rn(ry);
    hi = ((uint32_t)__bfloat16_as_ushort(hy) << 16) | (uint32_t)__bfloat16_as_ushort(hx);
    lo = ((uint32_t)__bfloat16_as_ushort(ly) << 16) | (uint32_t)__bfloat16_as_ushort(lx);
}

__device__ __forceinline__ void mma_bf16(float* c, const uint32_t* a, const uint32_t* b) {
    asm volatile(
        "mma.sync.aligned.m16n8k16.row.col.f32.bf16.bf16.f32 "
        "{%0,%1,%2,%3}, {%4,%5,%6,%7}, {%8,%9}, {%0,%1,%2,%3};\n"
        : "+f"(c[0]), "+f"(c[1]), "+f"(c[2]), "+f"(c[3])
        : "r"(a[0]), "r"(a[1]), "r"(a[2]), "r"(a[3]), "r"(b[0]), "r"(b[1]));
}

// ============================================================================
// Split-bf16 tensor-core GEMM.  Block 128x128, BK=32, 256 threads (8 warps,
// warp tile 64x32).  Shared layout: [row][16 words], word = packed bf16 k-pair,
// swizzle: word index ^ (2*(row&7)).  C = A @ B (+ optional transpose of B).
// Requires M % 128 == 0 and K % 32 == 0 (true for every call here).
// ============================================================================

// NN:  A[M,K] row-major, B[K,N] row-major
__global__ __launch_bounds__(256, 2) void tgemm_nn(
    const float* __restrict__ A, const float* __restrict__ B, float* __restrict__ C,
    int M, int N, int K, int lda, int ldb, int ldc,
    long sA, long sB, long sC, int truncK)
{
    A += (long)blockIdx.z * sA;
    B += (long)blockIdx.z * sB;
    C += (long)blockIdx.z * sC;
    const int bx = blockIdx.x, by = blockIdx.y;
    if (truncK) { int ke = (by + 1) * 128; if (ke < K) K = ke; }

    __shared__ uint32_t Ah[128 * 16], Al[128 * 16], Bh[128 * 16], Bl[128 * 16];

    const int tid = threadIdx.x, lane = tid & 31, warp = tid >> 5;
    const int wm = warp & 1, wn = warp >> 1;
    const int g = lane >> 2, t = lane & 3;

    float acc[4][4][4] = {};

    // A load mapping: i=0..3 -> m=(tid>>3)+32i, f4 group = tid&7
    const int amL = tid >> 3, af4 = tid & 7;
    // B load mapping: i=0..1 -> kp=(tid&7)+8i, n4 = tid>>3
    const int bn4 = tid >> 3, bkp = tid & 7;

    for (int k0 = 0; k0 < K; k0 += 32) {
        // ---- stage A tile [128 x 32] ----
        #pragma unroll
        for (int i = 0; i < 4; i++) {
            int m = amL + 32 * i;
            const float4 v = *(const float4*)(A + (long)(by * 128 + m) * lda + k0 + af4 * 4);
            uint32_t h0, l0, h1, l1;
            split2(v.x, v.y, h0, l0);
            split2(v.z, v.w, h1, l1);
            int off = m * 16 + ((af4 * 2) ^ (2 * (m & 7)));
            Ah[off] = h0; Ah[off + 1] = h1;
            Al[off] = l0; Al[off + 1] = l1;
        }
        // ---- stage B tile [32 x 128] with transpose to [n][k] ----
        #pragma unroll
        for (int i = 0; i < 2; i++) {
            int kp = bkp + 8 * i;
            int nloc = bn4 * 4;
            int nglob = bx * 128 + nloc;
            const float* r0 = B + (long)(k0 + 2 * kp) * ldb + nglob;
            const float* r1 = r0 + ldb;
            float4 v0, v1;
            if (nglob + 3 < N) {
                v0 = *(const float4*)r0;
                v1 = *(const float4*)r1;
            } else {
                v0.x = (nglob + 0 < N) ? r0[0] : 0.f; v1.x = (nglob + 0 < N) ? r1[0] : 0.f;
                v0.y = (nglob + 1 < N) ? r0[1] : 0.f; v1.y = (nglob + 1 < N) ? r1[1] : 0.f;
                v0.z = (nglob + 2 < N) ? r0[2] : 0.f; v1.z = (nglob + 2 < N) ? r1[2] : 0.f;
                v0.w = (nglob + 3 < N) ? r0[3] : 0.f; v1.w = (nglob + 3 < N) ? r1[3] : 0.f;
            }
            const float e0[4] = {v0.x, v0.y, v0.z, v0.w};
            const float e1[4] = {v1.x, v1.y, v1.z, v1.w};
            #pragma unroll
            for (int j = 0; j < 4; j++) {
                uint32_t hw, lw;
                split2(e0[j], e1[j], hw, lw);
                int nn = nloc + j;
                int off = nn * 16 + (kp ^ (2 * (nn & 7)));
                Bh[off] = hw; Bl[off] = lw;
            }
        }
        __syncthreads();

        // ---- compute: 2 k16-steps ----
        #pragma unroll
        for (int ks = 0; ks < 2; ks++) {
            const int i0 = (ks * 8 + t) ^ (2 * g);
            const int i1 = (ks * 8 + t + 4) ^ (2 * g);
            uint32_t bh[4][2], bl[4][2];
            #pragma unroll
            for (int nt = 0; nt < 4; nt++) {
                int bo = (wn * 32 + nt * 8 + g) * 16;
                bh[nt][0] = Bh[bo + i0]; bh[nt][1] = Bh[bo + i1];
                bl[nt][0] = Bl[bo + i0]; bl[nt][1] = Bl[bo + i1];
            }
            #pragma unroll
            for (int mt = 0; mt < 4; mt++) {
                int ao = (wm * 64 + mt * 16 + g) * 16;
                uint32_t ah[4] = {Ah[ao + i0], Ah[ao + 128 + i0], Ah[ao + i1], Ah[ao + 128 + i1]};
                uint32_t al[4] = {Al[ao + i0], Al[ao + 128 + i0], Al[ao + i1], Al[ao + 128 + i1]};
                #pragma unroll
                for (int nt = 0; nt < 4; nt++) {
                    mma_bf16(acc[mt][nt], ah, bh[nt]);
                    mma_bf16(acc[mt][nt], ah, bl[nt]);
                    mma_bf16(acc[mt][nt], al, bh[nt]);
                }
            }
        }
        __syncthreads();
    }

    // ---- epilogue ----
    #pragma unroll
    for (int mt = 0; mt < 4; mt++) {
        int r = by * 128 + wm * 64 + mt * 16 + g;
        #pragma unroll
        for (int nt = 0; nt < 4; nt++) {
            int c = bx * 128 + wn * 32 + nt * 8 + 2 * t;
            if (c < N) {
                *(float2*)&C[(long)r * ldc + c]       = make_float2(acc[mt][nt][0], acc[mt][nt][1]);
                *(float2*)&C[(long)(r + 8) * ldc + c] = make_float2(acc[mt][nt][2], acc[mt][nt][3]);
            }
        }
    }
}

// NT:  A[M,K] row-major, B[N,K] row-major (C = A @ B^T), optional causal skip
__global__ __launch_bounds__(256, 2) void tgemm_nt(
    const float* __restrict__ A, const float* __restrict__ B, float* __restrict__ C,
    int M, int N, int K, int lda, int ldb, int ldc,
    long sA, long sB, long sC, int causal)
{
    const int bx = blockIdx.x, by = blockIdx.y;
    if (causal && bx > by) return;

    A += (long)blockIdx.z * sA;
    B += (long)blockIdx.z * sB;
    C += (long)blockIdx.z * sC;

    __shared__ uint32_t Ah[128 * 16], Al[128 * 16], Bh[128 * 16], Bl[128 * 16];

    const int tid = threadIdx.x, lane = tid & 31, warp = tid >> 5;
    const int wm = warp & 1, wn = warp >> 1;
    const int g = lane >> 2, t = lane & 3;

    float acc[4][4][4] = {};

    const int amL = tid >> 3, af4 = tid & 7;

    for (int k0 = 0; k0 < K; k0 += 32) {
        #pragma unroll
        for (int i = 0; i < 4; i++) {
            int m = amL + 32 * i;
            const float4 v = *(const float4*)(A + (long)(by * 128 + m) * lda + k0 + af4 * 4);
            uint32_t h0, l0, h1, l1;
            split2(v.x, v.y, h0, l0);
            split2(v.z, v.w, h1, l1);
            int off = m * 16 + ((af4 * 2) ^ (2 * (m & 7)));
            Ah[off] = h0; Ah[off + 1] = h1;
            Al[off] = l0; Al[off + 1] = l1;
        }
        #pragma unroll
        for (int i = 0; i < 4; i++) {
            int n = amL + 32 * i;
            int nglob = bx * 128 + n;
            float4 v = make_float4(0.f, 0.f, 0.f, 0.f);
            if (nglob < N)
                v = *(const float4*)(B + (long)nglob * ldb + k0 + af4 * 4);
            uint32_t h0, l0, h1, l1;
            split2(v.x, v.y, h0, l0);
            split2(v.z, v.w, h1, l1);
            int off = n * 16 + ((af4 * 2) ^ (2 * (n & 7)));
            Bh[off] = h0; Bh[off + 1] = h1;
            Bl[off] = l0; Bl[off + 1] = l1;
        }
        __syncthreads();

        #pragma unroll
        for (int ks = 0; ks < 2; ks++) {
            const int i0 = (ks * 8 + t) ^ (2 * g);
            const int i1 = (ks * 8 + t + 4) ^ (2 * g);
            uint32_t bh[4][2], bl[4][2];
            #pragma unroll
            for (int nt = 0; nt < 4; nt++) {
                int bo = (wn * 32 + nt * 8 + g) * 16;
                bh[nt][0] = Bh[bo + i0]; bh[nt][1] = Bh[bo + i1];
                bl[nt][0] = Bl[bo + i0]; bl[nt][1] = Bl[bo + i1];
            }
            #pragma unroll
            for (int mt = 0; mt < 4; mt++) {
                int ao = (wm * 64 + mt * 16 + g) * 16;
                uint32_t ah[4] = {Ah[ao + i0], Ah[ao + 128 + i0], Ah[ao + i1], Ah[ao + 128 + i1]};
                uint32_t al[4] = {Al[ao + i0], Al[ao + 128 + i0], Al[ao + i1], Al[ao + 128 + i1]};
                #pragma unroll
                for (int nt = 0; nt < 4; nt++) {
                    mma_bf16(acc[mt][nt], ah, bh[nt]);
                    mma_bf16(acc[mt][nt], ah, bl[nt]);
                    mma_bf16(acc[mt][nt], al, bh[nt]);
                }
            }
        }
        __syncthreads();
    }

    #pragma unroll
    for (int mt = 0; mt < 4; mt++) {
        int r = by * 128 + wm * 64 + mt * 16 + g;
        #pragma unroll
        for (int nt = 0; nt < 4; nt++) {
            int c = bx * 128 + wn * 32 + nt * 8 + 2 * t;
            if (c < N) {
                *(float2*)&C[(long)r * ldc + c]       = make_float2(acc[mt][nt][0], acc[mt][nt][1]);
                *(float2*)&C[(long)(r + 8) * ldc + c] = make_float2(acc[mt][nt][2], acc[mt][nt][3]);
            }
        }
    }
}

// ---------------- RMSNorm ----------------
__global__ void rmsnorm_k(float* __restrict__ x, const float* __restrict__ w, int N, int ld)
{
    float* p = x + (long)blockIdx.x * ld;
    __shared__ float red[8];
    __shared__ float bc;
    const int lane = threadIdx.x & 31, wid = threadIdx.x >> 5;

    float s = 0.f;
    for (int j = threadIdx.x; j < N; j += blockDim.x) { float v = p[j]; s += v * v; }
    #pragma unroll
    for (int o = 16; o; o >>= 1) s += __shfl_xor_sync(0xffffffffu, s, o);
    if (lane == 0) red[wid] = s;
    __syncthreads();
    if (threadIdx.x == 0) {
        float v = 0.f;
        for (int wI = 0; wI < 8; wI++) v += red[wI];
        bc = rsqrtf(v / N + 1e-6f);
    }
    __syncthreads();
    float r = bc;
    for (int j = threadIdx.x; j < N; j += blockDim.x) p[j] = p[j] * r * w[j];
}

// ---------------- neox RoPE ----------------
__global__ void rope_q_k(float* __restrict__ q, const int* __restrict__ pos)
{
    const int tt = blockIdx.x, h = blockIdx.y, i = threadIdx.x;
    double inv = pow(10000.0, -(double)i / 32.0);
    double sd, cd;
    sincos((double)pos[tt] * inv, &sd, &cd);
    float c = (float)cd, s = (float)sd;
    float* p = q + (long)tt * HDQ + h * DQ + DN;
    float x1 = p[i], x2 = p[i + 32];
    p[i]      = x1 * c - x2 * s;
    p[i + 32] = x2 * c + x1 * s;
}

__global__ void rope_kpe_k(float* __restrict__ lat, const int* __restrict__ pos)
{
    const int tt = blockIdx.x, i = threadIdx.x;
    double inv = pow(10000.0, -(double)i / 32.0);
    double sd, cd;
    sincos((double)pos[tt] * inv, &sd, &cd);
    float c = (float)cd, s = (float)sd;
    float* p = lat + (long)tt * LATW + DKV;
    float x1 = p[i], x2 = p[i + 32];
    p[i]      = x1 * c - x2 * s;
    p[i + 32] = x2 * c + x1 * s;
}

// ---------------- assemble K ----------------
__global__ void build_K_k(const float* __restrict__ kv, const float* __restrict__ lat,
                          float* __restrict__ Kc)
{
    const int tt = blockIdx.x;
    for (int x = threadIdx.x; x < HDQ; x += blockDim.x) {
        int h = x >> 8, d = x & 255;
        float v = (d < DN) ? kv[(long)tt * KVW + h * (DN + DV) + d]
                           : lat[(long)tt * LATW + DKV + (d - DN)];
        Kc[(long)tt * HDQ + x] = v;
    }
}

// ---------------- causal softmax ----------------
__global__ void softmax_causal_k(float* __restrict__ S)
{
    const float scale = 0.0625f;
    const int tt = blockIdx.x, h = blockIdx.y;
    float* row = S + ((long)h * T + tt) * (long)T;
    const int n = tt + 1;
    __shared__ float red[8];
    __shared__ float bc;
    const int lane = threadIdx.x & 31, wid = threadIdx.x >> 5;

    float m = -3.4e38f;
    for (int j = threadIdx.x; j < n; j += blockDim.x) m = fmaxf(m, row[j]);
    #pragma unroll
    for (int o = 16; o; o >>= 1) m = fmaxf(m, __shfl_xor_sync(0xffffffffu, m, o));
    if (lane == 0) red[wid] = m;
    __syncthreads();
    if (threadIdx.x == 0) {
        float v = red[0];
        for (int wI = 1; wI < 8; wI++) v = fmaxf(v, red[wI]);
        bc = v;
    }
    __syncthreads();
    m = bc;
    __syncthreads();

    float s = 0.f;
    for (int j = threadIdx.x; j < n; j += blockDim.x) {
        float e = expf((row[j] - m) * scale);
        row[j] = e;
        s += e;
    }
    #pragma unroll
    for (int o = 16; o; o >>= 1) s += __shfl_xor_sync(0xffffffffu, s, o);
    if (lane == 0) red[wid] = s;
    __syncthreads();
    if (threadIdx.x == 0) {
        float v = 0.f;
        for (int wI = 0; wI < 8; wI++) v += red[wI];
        bc = 1.f / v;
    }
    __syncthreads();
    float inv = bc;
    for (int j = threadIdx.x; j < n; j += blockDim.x) row[j] *= inv;
    for (int j = n + threadIdx.x; j < T; j += blockDim.x) row[j] = 0.f;
}

// ---------------- launch ----------------
extern "C" void kernel_launch(void* const* d_in, const int* in_sizes, int n_in,
                              void* d_out, int out_size)
{
    (void)in_sizes; (void)n_in; (void)out_size;
    const float* hidden = (const float*)d_in[0];
    const int*   pos    = (const int*)  d_in[1];
    const float* wq_a   = (const float*)d_in[2];
    const float* q_ln   = (const float*)d_in[3];
    const float* wq_b   = (const float*)d_in[4];
    const float* wkv_a  = (const float*)d_in[5];
    const float* kv_ln  = (const float*)d_in[6];
    const float* wkv_b  = (const float*)d_in[7];
    const float* wo     = (const float*)d_in[8];
    float* out = (float*)d_out;

    float *qlora, *latent, *q, *kv, *Kc, *S, *O;
    cudaGetSymbolAddress((void**)&qlora,  g_qlora);
    cudaGetSymbolAddress((void**)&latent, g_latent);
    cudaGetSymbolAddress((void**)&q,      g_q);
    cudaGetSymbolAddress((void**)&kv,     g_kv);
    cudaGetSymbolAddress((void**)&Kc,     g_K);
    cudaGetSymbolAddress((void**)&S,      g_S);
    cudaGetSymbolAddress((void**)&O,      g_O);

    dim3 blk(256);

    // q lora down + kv latent down
    tgemm_nn<<<dim3(QLORA / 128, T / 128, 1), blk>>>(hidden, wq_a, qlora,
        T, QLORA, HID, HID, QLORA, QLORA, 0, 0, 0, 0);
    tgemm_nn<<<dim3((LATW + 127) / 128, T / 128, 1), blk>>>(hidden, wkv_a, latent,
        T, LATW, HID, HID, LATW, LATW, 0, 0, 0, 0);

    // rmsnorms
    rmsnorm_k<<<T, 256>>>(qlora, q_ln, QLORA, QLORA);
    rmsnorm_k<<<T, 256>>>(latent, kv_ln, DKV, LATW);

    // up projections
    tgemm_nn<<<dim3(HDQ / 128, T / 128, 1), blk>>>(qlora, wq_b, q,
        T, HDQ, QLORA, QLORA, HDQ, HDQ, 0, 0, 0, 0);
    tgemm_nn<<<dim3(KVW / 128, T / 128, 1), blk>>>(latent, wkv_b, kv,
        T, KVW, DKV, LATW, KVW, KVW, 0, 0, 0, 0);

    // rope
    rope_q_k<<<dim3(T, NH), 32>>>(q, pos);
    rope_kpe_k<<<T, 32>>>(latent, pos);

    // assemble K [T, H*256]
    build_K_k<<<T, 256>>>(kv, latent, Kc);

    // scores: S_h = Q_h @ K_h^T (batched over heads, causal skip)
    tgemm_nt<<<dim3(T / 128, T / 128, NH), blk>>>(q, Kc, S,
        T, T, DQ, HDQ, HDQ, T, (long)DQ, (long)DQ, (long)T * T, 1);

    // causal softmax
    softmax_causal_k<<<dim3(T, NH), 256>>>(S);

    // O_h = P_h @ V_h (causal K truncation)
    tgemm_nn<<<dim3(DV / 128, T / 128, NH), blk>>>(S, kv + DN, O,
        T, DV, T, T, KVW, HDQ, (long)T * T, (long)(DN + DV), (long)DV, 1);

    // final projection
    tgemm_nn<<<dim3(HID / 128, T / 128, 1), blk>>>(O, wo, out,
        T, HID, HDQ, HDQ, HID, HID, 0, 0, 0, 0);
}

// round 3
// speedup vs baseline: 2.8930x; 1.3326x over previous
#include <cuda_runtime.h>
#include <cuda_bf16.h>
#include <math.h>
#include <stdint.h>

// ---------------- problem constants ----------------
constexpr int T    = 2048;
constexpr int HID  = 4096;
constexpr int NH   = 32;
constexpr int DQ   = 256;
constexpr int DN   = 192;
constexpr int DR   = 64;
constexpr int DV   = 256;
constexpr int DKV  = 512;
constexpr int QLORA= 2048;
constexpr int HDQ  = NH * DQ;        // 8192
constexpr int KVW  = NH * (DN + DV); // 14336
constexpr int LATW = DKV + DR;       // 576

// ---------------- fp32 scratch ----------------
__device__ float g_qlora[(size_t)T * QLORA];
__device__ float g_latent[(size_t)T * LATW];
__device__ float g_q[(size_t)T * HDQ];
__device__ float g_kv[(size_t)T * KVW];
__device__ float g_S[(size_t)NH * T * T];
__device__ float g_O[(size_t)T * HDQ];

// ---------------- split-bf16 planes ----------------
__device__ __nv_bfloat16 g_hid_p [2][(size_t)T * HID];
__device__ __nv_bfloat16 g_wqaT  [2][(size_t)QLORA * HID];
__device__ __nv_bfloat16 g_wkvaT [2][(size_t)LATW * HID];
__device__ __nv_bfloat16 g_wqbT  [2][(size_t)HDQ * QLORA];
__device__ __nv_bfloat16 g_wkvbT [2][(size_t)KVW * DKV];
__device__ __nv_bfloat16 g_woT   [2][(size_t)HID * HDQ];
__device__ __nv_bfloat16 g_qlo_p [2][(size_t)T * QLORA];
__device__ __nv_bfloat16 g_lat_p [2][(size_t)T * DKV];
__device__ __nv_bfloat16 g_q_p   [2][(size_t)T * HDQ];
__device__ __nv_bfloat16 g_Kc_p  [2][(size_t)T * HDQ];
__device__ __nv_bfloat16 g_Vt_p  [2][(size_t)NH * DV * T];
__device__ __nv_bfloat16 g_P_p   [2][(size_t)NH * T * T];
__device__ __nv_bfloat16 g_O_p   [2][(size_t)T * HDQ];

// ---------------- helpers ----------------
__device__ __forceinline__ void splitf(float v, __nv_bfloat16& h, __nv_bfloat16& l) {
    h = __float2bfloat16_rn(v);
    l = __float2bfloat16_rn(v - __bfloat162float(h));
}

__device__ __forceinline__ void mma_bf16(float* c, const uint32_t* a, const uint32_t* b) {
    asm volatile(
        "mma.sync.aligned.m16n8k16.row.col.f32.bf16.bf16.f32 "
        "{%0,%1,%2,%3}, {%4,%5,%6,%7}, {%8,%9}, {%0,%1,%2,%3};\n"
        : "+f"(c[0]), "+f"(c[1]), "+f"(c[2]), "+f"(c[3])
        : "r"(a[0]), "r"(a[1]), "r"(a[2]), "r"(a[3]), "r"(b[0]), "r"(b[1]));
}

__device__ __forceinline__ void ldsm4(uint32_t& r0, uint32_t& r1, uint32_t& r2, uint32_t& r3, uint32_t a) {
    asm volatile("ldmatrix.sync.aligned.m8n8.x4.shared.b16 {%0,%1,%2,%3}, [%4];"
        : "=r"(r0), "=r"(r1), "=r"(r2), "=r"(r3) : "r"(a));
}

__device__ __forceinline__ void cp16(uint32_t d, const void* s) {
    asm volatile("cp.async.cg.shared.global [%0], [%1], 16;" :: "r"(d), "l"(s));
}

// ============================================================================
// Uniform split-bf16 GEMM: C = A @ B^T on hi/lo planes.
// A planes [.,lda] row-major (row m holds k), B planes [.,ldb] (row n holds k).
// Block 128x128, BK=32, 256 threads, cp.async double-buffered, ldmatrix frags.
// smem: 2 stages x 4 tiles (Ah,Al,Bh,Bl) x (128 rows x 80B)   = 81920 bytes.
// Requires M%128==0, K%32==0.
// ============================================================================
constexpr int TILE_B   = 128 * 80;       // one plane tile
constexpr int STAGE_B  = 4 * TILE_B;     // 4 planes
constexpr int SMEM_GEMM = 2 * STAGE_B;   // 81920

__global__ __launch_bounds__(256, 2) void tgemm_pl(
    const __nv_bfloat16* __restrict__ Ah, const __nv_bfloat16* __restrict__ Al,
    const __nv_bfloat16* __restrict__ Bh, const __nv_bfloat16* __restrict__ Bl,
    float* __restrict__ C,
    int M, int N, int K, int lda, int ldb, int ldc,
    long sA, long sB, long sC, int causal, int truncK)
{
    const int bx = blockIdx.x, by = blockIdx.y;
    if (causal && bx > by) return;
    Ah += (long)blockIdx.z * sA;  Al += (long)blockIdx.z * sA;
    Bh += (long)blockIdx.z * sB;  Bl += (long)blockIdx.z * sB;
    C  += (long)blockIdx.z * sC;
    if (truncK) { int ke = (by + 1) * 128; if (ke < K) K = ke; }

    extern __shared__ char smem[];
    const uint32_t sb = (uint32_t)__cvta_generic_to_shared(smem);

    const int tid = threadIdx.x, lane = tid & 31, warp = tid >> 5;
    const int wm = warp & 1, wn = warp >> 1;
    const int g = lane >> 2, t4 = lane & 3;

    // cp.async coords: chunk = tid + c*256; row = chunk>>2, col16 = chunk&3
    const int r0 = tid >> 2, c4 = tid & 3;
    const int Nm1 = N - 1;

    // ldmatrix lane offsets
    const int lr  = (lane & 7) + ((lane >> 3) & 1) * 8;
    const int lkb = (lane >> 4) * 16;
    const uint32_t aBase = sb + (uint32_t)((wm * 64 + lr) * 80 + lkb);
    const uint32_t bBase = sb + (uint32_t)(2 * TILE_B + (wn * 32 + lr) * 80 + lkb);

    float acc[4][4][4] = {};
    const int nchunks = K / 32;

    // ---- prefetch chunk 0 ----
    {
        #pragma unroll
        for (int c = 0; c < 2; c++) {
            int row = r0 + c * 64;
            uint32_t ds = sb + (uint32_t)(row * 80 + c4 * 16);
            long aoff = (long)(by * 128 + row) * lda + c4 * 8;
            cp16(ds,              Ah + aoff);
            cp16(ds + TILE_B,     Al + aoff);
            int nr = bx * 128 + row; if (nr > Nm1) nr = Nm1;
            long boff = (long)nr * ldb + c4 * 8;
            cp16(ds + 2 * TILE_B, Bh + boff);
            cp16(ds + 3 * TILE_B, Bl + boff);
        }
        asm volatile("cp.async.commit_group;");
    }

    for (int i = 0; i < nchunks; i++) {
        if (i + 1 < nchunks) {
            const int k0 = (i + 1) * 32;
            const uint32_t st = (uint32_t)(((i + 1) & 1) * STAGE_B);
            #pragma unroll
            for (int c = 0; c < 2; c++) {
                int row = r0 + c * 64;
                uint32_t ds = sb + st + (uint32_t)(row * 80 + c4 * 16);
                long aoff = (long)(by * 128 + row) * lda + k0 + c4 * 8;
                cp16(ds,              Ah + aoff);
                cp16(ds + TILE_B,     Al + aoff);
                int nr = bx * 128 + row; if (nr > Nm1) nr = Nm1;
                long boff = (long)nr * ldb + k0 + c4 * 8;
                cp16(ds + 2 * TILE_B, Bh + boff);
                cp16(ds + 3 * TILE_B, Bl + boff);
            }
        }
        asm volatile("cp.async.commit_group;");
        asm volatile("cp.async.wait_group 1;");
        __syncthreads();

        const uint32_t sof = (uint32_t)((i & 1) * STAGE_B);
        #pragma unroll
        for (int ks = 0; ks < 2; ks++) {
            uint32_t bh[4][2], bl[4][2];
            #pragma unroll
            for (int p = 0; p < 2; p++) {
                uint32_t ad = bBase + sof + (uint32_t)(p * 16 * 80 + ks * 32);
                uint32_t x0, x1, x2, x3;
                ldsm4(x0, x1, x2, x3, ad);
                bh[2*p][0] = x0; bh[2*p+1][0] = x1; bh[2*p][1] = x2; bh[2*p+1][1] = x3;
                ldsm4(x0, x1, x2, x3, ad + TILE_B);
                bl[2*p][0] = x0; bl[2*p+1][0] = x1; bl[2*p][1] = x2; bl[2*p+1][1] = x3;
            }
            #pragma unroll
            for (int mt = 0; mt < 4; mt++) {
                uint32_t ah[4], al[4];
                uint32_t ad = aBase + sof + (uint32_t)(mt * 16 * 80 + ks * 32);
                ldsm4(ah[0], ah[1], ah[2], ah[3], ad);
                ldsm4(al[0], al[1], al[2], al[3], ad + TILE_B);
                #pragma unroll
                for (int nt = 0; nt < 4; nt++) {
                    mma_bf16(acc[mt][nt], ah, bh[nt]);
                    mma_bf16(acc[mt][nt], ah, bl[nt]);
                    mma_bf16(acc[mt][nt], al, bh[nt]);
                }
            }
        }
        __syncthreads();
    }

    #pragma unroll
    for (int mt = 0; mt < 4; mt++) {
        int r = by * 128 + wm * 64 + mt * 16 + g;
        #pragma unroll
        for (int nt = 0; nt < 4; nt++) {
            int c = bx * 128 + wn * 32 + nt * 8 + 2 * t4;
            if (c < N) {
                *(float2*)&C[(long)r * ldc + c]       = make_float2(acc[mt][nt][0], acc[mt][nt][1]);
                *(float2*)&C[(long)(r + 8) * ldc + c] = make_float2(acc[mt][nt][2], acc[mt][nt][3]);
            }
        }
    }
}

// ---------------- fp32 -> planes (same layout) ----------------
__global__ void conv_pl_k(const float* __restrict__ x, __nv_bfloat16* __restrict__ h,
                          __nv_bfloat16* __restrict__ l, long n)
{
    long i = (long)blockIdx.x * blockDim.x + threadIdx.x;
    long stride = (long)gridDim.x * blockDim.x;
    for (; i < n; i += stride) {
        __nv_bfloat16 hh, ll;
        splitf(x[i], hh, ll);
        h[i] = hh; l[i] = ll;
    }
}

// ---------------- fp32 [R,C] -> planes transposed [C,R] ----------------
__global__ void conv_tr_k(const float* __restrict__ x, __nv_bfloat16* __restrict__ h,
                          __nv_bfloat16* __restrict__ l, int R, int C)
{
    __shared__ float tile[32][33];
    const int c0 = blockIdx.x * 32, rr0 = blockIdx.y * 32;
    const int tx = threadIdx.x & 31, ty = threadIdx.x >> 5;
    #pragma unroll
    for (int i = 0; i < 4; i++) {
        int r = rr0 + ty + i * 8;
        tile[ty + i * 8][tx] = x[(long)r * C + c0 + tx];
    }
    __syncthreads();
    #pragma unroll
    for (int i = 0; i < 4; i++) {
        int c = c0 + ty + i * 8;
        float v = tile[tx][ty + i * 8];
        long o = (long)c * R + rr0 + tx;
        __nv_bfloat16 hh, ll;
        splitf(v, hh, ll);
        h[o] = hh; l[o] = ll;
    }
}

// ---------------- RMSNorm fp32 in -> planes out ----------------
__global__ void rmsnorm_pl_k(const float* __restrict__ x, const float* __restrict__ w,
                             __nv_bfloat16* __restrict__ h, __nv_bfloat16* __restrict__ l,
                             int N, int ldin)
{
    const float* p = x + (long)blockIdx.x * ldin;
    __shared__ float red[8];
    __shared__ float bc;
    const int lane = threadIdx.x & 31, wid = threadIdx.x >> 5;

    float s = 0.f;
    for (int j = threadIdx.x; j < N; j += blockDim.x) { float v = p[j]; s += v * v; }
    #pragma unroll
    for (int o = 16; o; o >>= 1) s += __shfl_xor_sync(0xffffffffu, s, o);
    if (lane == 0) red[wid] = s;
    __syncthreads();
    if (threadIdx.x == 0) {
        float v = 0.f;
        for (int wI = 0; wI < 8; wI++) v += red[wI];
        bc = rsqrtf(v / N + 1e-6f);
    }
    __syncthreads();
    float r = bc;
    long ob = (long)blockIdx.x * N;
    for (int j = threadIdx.x; j < N; j += blockDim.x) {
        __nv_bfloat16 hh, ll;
        splitf(p[j] * r * w[j], hh, ll);
        h[ob + j] = hh; l[ob + j] = ll;
    }
}

// ---------------- rope k_pe in-place (fp32 latent cols 512..575) ----------------
__global__ void rope_kpe_k(float* __restrict__ lat, const int* __restrict__ pos)
{
    const int tt = blockIdx.x, i = threadIdx.x;
    double inv = pow(10000.0, -(double)i / 32.0);
    double sd, cd;
    sincos((double)pos[tt] * inv, &sd, &cd);
    float c = (float)cd, s = (float)sd;
    float* p = lat + (long)tt * LATW + DKV;
    float x1 = p[i], x2 = p[i + 32];
    p[i]      = x1 * c - x2 * s;
    p[i + 32] = x2 * c + x1 * s;
}

// ---------------- q: rope fused + planes out ----------------
__global__ void rope_conv_q_k(const float* __restrict__ q, const int* __restrict__ pos,
                              __nv_bfloat16* __restrict__ h, __nv_bfloat16* __restrict__ l)
{
    const int tt = blockIdx.x;
    __shared__ float cs[32], sn[32];
    if (threadIdx.x < 32) {
        double inv = pow(10000.0, -(double)threadIdx.x / 32.0);
        double sd, cd;
        sincos((double)pos[tt] * inv, &sd, &cd);
        cs[threadIdx.x] = (float)cd; sn[threadIdx.x] = (float)sd;
    }
    __syncthreads();
    const float* row = q + (long)tt * HDQ;
    long ob = (long)tt * HDQ;
    for (int x = threadIdx.x; x < HDQ; x += blockDim.x) {
        int d = x & 255;
        float v;
        if (d < DN)            v = row[x];
        else if (d < DN + 32) { int i = d - DN;       v = row[x] * cs[i] - row[x + 32] * sn[i]; }
        else                  { int i = d - DN - 32;  v = row[x] * cs[i] + row[x - 32] * sn[i]; }
        __nv_bfloat16 hh, ll;
        splitf(v, hh, ll);
        h[ob + x] = hh; l[ob + x] = ll;
    }
}

// ---------------- K assembly -> planes [T][H*256] ----------------
__global__ void build_K_pl_k(const float* __restrict__ kv, const float* __restrict__ lat,
                             __nv_bfloat16* __restrict__ h, __nv_bfloat16* __restrict__ l)
{
    const int tt = blockIdx.x;
    long ob = (long)tt * HDQ;
    for (int x = threadIdx.x; x < HDQ; x += blockDim.x) {
        int hd = x >> 8, d = x & 255;
        float v = (d < DN) ? kv[(long)tt * KVW + hd * (DN + DV) + d]
                           : lat[(long)tt * LATW + DKV + (d - DN)];
        __nv_bfloat16 hh, ll;
        splitf(v, hh, ll);
        h[ob + x] = hh; l[ob + x] = ll;
    }
}

// ---------------- V transpose per head -> planes [h][DV][T] ----------------
__global__ void transpose_v_pl_k(const float* __restrict__ kv,
                                 __nv_bfloat16* __restrict__ h, __nv_bfloat16* __restrict__ l)
{
    __shared__ float tile[32][33];
    const int d0 = blockIdx.x * 32, t0 = blockIdx.y * 32, hd = blockIdx.z;
    const int tx = threadIdx.x & 31, ty = threadIdx.x >> 5;
    #pragma unroll
    for (int i = 0; i < 4; i++) {
        int tr = t0 + ty + i * 8;
        tile[ty + i * 8][tx] = kv[(long)tr * KVW + hd * (DN + DV) + DN + d0 + tx];
    }
    __syncthreads();
    #pragma unroll
    for (int i = 0; i < 4; i++) {
        int d = d0 + ty + i * 8;
        float v = tile[tx][ty + i * 8];
        long o = (long)hd * DV * T + (long)d * T + t0 + tx;
        __nv_bfloat16 hh, ll;
        splitf(v, hh, ll);
        h[o] = hh; l[o] = ll;
    }
}

// ---------------- causal softmax: fp32 scores -> P planes ----------------
__global__ void softmax_pl_k(float* __restrict__ S,
                             __nv_bfloat16* __restrict__ Ph, __nv_bfloat16* __restrict__ Pl)
{
    const float scale = 0.0625f;   // DQ^-0.5
    const int tt = blockIdx.x, hd = blockIdx.y;
    long rb = ((long)hd * T + tt) * (long)T;
    float* row = S + rb;
    const int n = tt + 1;
    __shared__ float red[8];
    __shared__ float bc;
    const int lane = threadIdx.x & 31, wid = threadIdx.x >> 5;

    float m = -3.4e38f;
    for (int j = threadIdx.x; j < n; j += blockDim.x) m = fmaxf(m, row[j]);
    #pragma unroll
    for (int o = 16; o; o >>= 1) m = fmaxf(m, __shfl_xor_sync(0xffffffffu, m, o));
    if (lane == 0) red[wid] = m;
    __syncthreads();
    if (threadIdx.x == 0) {
        float v = red[0];
        for (int wI = 1; wI < 8; wI++) v = fmaxf(v, red[wI]);
        bc = v;
    }
    __syncthreads();
    m = bc;
    __syncthreads();

    float s = 0.f;
    for (int j = threadIdx.x; j < n; j += blockDim.x) {
        float e = expf((row[j] - m) * scale);
        row[j] = e;
        s += e;
    }
    #pragma unroll
    for (int o = 16; o; o >>= 1) s += __shfl_xor_sync(0xffffffffu, s, o);
    if (lane == 0) red[wid] = s;
    __syncthreads();
    if (threadIdx.x == 0) {
        float v = 0.f;
        for (int wI = 0; wI < 8; wI++) v += red[wI];
        bc = 1.f / v;
    }
    __syncthreads();
    float inv = bc;
    for (int j = threadIdx.x; j < n; j += blockDim.x) {
        __nv_bfloat16 hh, ll;
        splitf(row[j] * inv, hh, ll);
        Ph[rb + j] = hh; Pl[rb + j] = ll;
    }
    const __nv_bfloat16 z = __float2bfloat16_rn(0.f);
    for (int j = n + threadIdx.x; j < T; j += blockDim.x) { Ph[rb + j] = z; Pl[rb + j] = z; }
}

// ---------------- launch ----------------
extern "C" void kernel_launch(void* const* d_in, const int* in_sizes, int n_in,
                              void* d_out, int out_size)
{
    (void)in_sizes; (void)n_in; (void)out_size;
    const float* hidden = (const float*)d_in[0];
    const int*   pos    = (const int*)  d_in[1];
    const float* wq_a   = (const float*)d_in[2];
    const float* q_ln   = (const float*)d_in[3];
    const float* wq_b   = (const float*)d_in[4];
    const float* wkv_a  = (const float*)d_in[5];
    const float* kv_ln  = (const float*)d_in[6];
    const float* wkv_b  = (const float*)d_in[7];
    const float* wo     = (const float*)d_in[8];
    float* out = (float*)d_out;

    static bool attr_done = false;
    cudaFuncSetAttribute(tgemm_pl, cudaFuncAttributeMaxDynamicSharedMemorySize, SMEM_GEMM);
    (void)attr_done;

    float *qlora, *latent, *q, *kv, *S, *O;
    cudaGetSymbolAddress((void**)&qlora,  g_qlora);
    cudaGetSymbolAddress((void**)&latent, g_latent);
    cudaGetSymbolAddress((void**)&q,      g_q);
    cudaGetSymbolAddress((void**)&kv,     g_kv);
    cudaGetSymbolAddress((void**)&S,      g_S);
    cudaGetSymbolAddress((void**)&O,      g_O);

    __nv_bfloat16 *hidp, *wqaT, *wkvaT, *wqbT, *wkvbT, *woT,
                  *qlop, *latp, *qp, *Kcp, *Vtp, *Pp, *Op;
    cudaGetSymbolAddress((void**)&hidp,  g_hid_p);
    cudaGetSymbolAddress((void**)&wqaT,  g_wqaT);
    cudaGetSymbolAddress((void**)&wkvaT, g_wkvaT);
    cudaGetSymbolAddress((void**)&wqbT,  g_wqbT);
    cudaGetSymbolAddress((void**)&wkvbT, g_wkvbT);
    cudaGetSymbolAddress((void**)&woT,   g_woT);
    cudaGetSymbolAddress((void**)&qlop,  g_qlo_p);
    cudaGetSymbolAddress((void**)&latp,  g_lat_p);
    cudaGetSymbolAddress((void**)&qp,    g_q_p);
    cudaGetSymbolAddress((void**)&Kcp,   g_Kc_p);
    cudaGetSymbolAddress((void**)&Vtp,   g_Vt_p);
    cudaGetSymbolAddress((void**)&Pp,    g_P_p);
    cudaGetSymbolAddress((void**)&Op,    g_O_p);

    #define PL(base, n) (base), ((base) + (size_t)(n))

    const size_t nHid = (size_t)T * HID,    nWqa = (size_t)QLORA * HID;
    const size_t nWkva= (size_t)LATW * HID, nWqb = (size_t)HDQ * QLORA;
    const size_t nWkvb= (size_t)KVW * DKV,  nWo  = (size_t)HID * HDQ;
    const size_t nQlo = (size_t)T * QLORA,  nLat = (size_t)T * DKV;
    const size_t nQ   = (size_t)T * HDQ,    nP   = (size_t)NH * T * T;
    const size_t nVt  = (size_t)NH * DV * T;

    dim3 blk(256);

    // ---- weight conversion + transpose ----
    conv_tr_k<<<dim3(QLORA/32, HID/32), blk>>>(wq_a,  PL(wqaT,  nWqa), HID, QLORA);
    conv_tr_k<<<dim3(LATW/32,  HID/32), blk>>>(wkv_a, PL(wkvaT, nWkva), HID, LATW);
    conv_tr_k<<<dim3(HDQ/32, QLORA/32), blk>>>(wq_b,  PL(wqbT,  nWqb), QLORA, HDQ);
    conv_tr_k<<<dim3(KVW/32,  DKV/32),  blk>>>(wkv_b, PL(wkvbT, nWkvb), DKV, KVW);
    conv_tr_k<<<dim3(HID/32,  HDQ/32),  blk>>>(wo,    PL(woT,   nWo),  HDQ, HID);
    conv_pl_k<<<2048, 256>>>(hidden, PL(hidp, nHid), (long)nHid);

    // ---- down projections ----
    tgemm_pl<<<dim3(QLORA/128, T/128), blk, SMEM_GEMM>>>(PL(hidp, nHid), PL(wqaT, nWqa),
        qlora, T, QLORA, HID, HID, HID, QLORA, 0, 0, 0, 0, 0);
    tgemm_pl<<<dim3((LATW+127)/128, T/128), blk, SMEM_GEMM>>>(PL(hidp, nHid), PL(wkvaT, nWkva),
        latent, T, LATW, HID, HID, HID, LATW, 0, 0, 0, 0, 0);

    // ---- norms + rope(k_pe) ----
    rmsnorm_pl_k<<<T, 256>>>(qlora, q_ln, PL(qlop, nQlo), QLORA, QLORA);
    rope_kpe_k<<<T, 32>>>(latent, pos);
    rmsnorm_pl_k<<<T, 256>>>(latent, kv_ln, PL(latp, nLat), DKV, LATW);

    // ---- up projections ----
    tgemm_pl<<<dim3(HDQ/128, T/128), blk, SMEM_GEMM>>>(PL(qlop, nQlo), PL(wqbT, nWqb),
        q, T, HDQ, QLORA, QLORA, QLORA, HDQ, 0, 0, 0, 0, 0);
    tgemm_pl<<<dim3(KVW/128, T/128), blk, SMEM_GEMM>>>(PL(latp, nLat), PL(wkvbT, nWkvb),
        kv, T, KVW, DKV, DKV, DKV, KVW, 0, 0, 0, 0, 0);

    // ---- q rope + planes; K assembly; V transpose ----
    rope_conv_q_k<<<T, 256>>>(q, pos, PL(qp, nQ));
    build_K_pl_k<<<T, 256>>>(kv, latent, PL(Kcp, nQ));
    transpose_v_pl_k<<<dim3(DV/32, T/32, NH), blk>>>(kv, PL(Vtp, nVt));

    // ---- scores (batched over heads, causal block skip) ----
    tgemm_pl<<<dim3(T/128, T/128, NH), blk, SMEM_GEMM>>>(
        qp,  qp + nQ,  Kcp, Kcp + nQ, S,
        T, T, DQ, HDQ, HDQ, T, (long)DQ, (long)DQ, (long)T * T, 1, 0);

    // ---- softmax -> P planes ----
    softmax_pl_k<<<dim3(T, NH), 256>>>(S, PL(Pp, nP));

    // ---- PV (causal K truncation) ----
    tgemm_pl<<<dim3(DV/128, T/128, NH), blk, SMEM_GEMM>>>(
        Pp, Pp + nP, Vtp, Vtp + nVt, O,
        T, DV, T, T, T, HDQ, (long)T * T, (long)DV * T, (long)DV, 0, 1);

    // ---- O planes + final projection ----
    conv_pl_k<<<2048, 256>>>(O, PL(Op, nQ), (long)nQ);
    tgemm_pl<<<dim3(HID/128, T/128), blk, SMEM_GEMM>>>(PL(Op, nQ), PL(woT, nWo),
        out, T, HID, HDQ, HDQ, HDQ, HID, 0, 0, 0, 0, 0);

    #undef PL
}